// round 1
// baseline (speedup 1.0000x reference)
#include <cuda_runtime.h>
#include <cuda_bf16.h>

// Problem constants
#define N_NODES 1024
#define BATCH   64
#define F_DIM   128          // INPUT_DIM + HID_DIM
#define NN      8192         // BATCH * F_DIM  (columns of diffusion GEMMs)
#define OUT_DIM 128
#define NUM_M   5            // x0, x1_s0, x2_s0, x1_s1, x2_s1

// Scratch: 5 diffusion states, each [N_NODES, BATCH, F_DIM] = [1024, 8192] f32 (32 MB)
__device__ __align__(16) float g_X[NUM_M][N_NODES * NN];

// ---------------------------------------------------------------------------
// Kernel 1: build X0[n][b][f] = concat(inputs[b][n][0:64], state[b][n][0:64])
// One float4 per thread; fully coalesced reads and writes.
// total float4s = 1024*64*128/4 = 2,097,152  -> grid 8192 x 256
// ---------------------------------------------------------------------------
__global__ void build_x0(const float* __restrict__ inputs,
                         const float* __restrict__ state) {
    int idx = blockIdx.x * blockDim.x + threadIdx.x;   // float4 index
    int f4 = idx & 31;            // 0..31  (128 floats / 4)
    int b  = (idx >> 5) & 63;     // 0..63
    int n  = idx >> 11;           // 0..1023
    float4 v;
    if (f4 < 16)
        v = reinterpret_cast<const float4*>(inputs)[b * 16384 + n * 16 + f4];
    else
        v = reinterpret_cast<const float4*>(state )[b * 16384 + n * 16 + (f4 - 16)];
    reinterpret_cast<float4*>(g_X[0])[idx] = v;
}

// ---------------------------------------------------------------------------
// Kernel 2: Chebyshev diffusion GEMM
//   C = alpha * A @ X  - (P ? P : 0)
//   A: [1024,1024] row-major, X/P/C: [1024, 8192] row-major (g_X slots)
// Tile: BM=BN=128, BK=8, 256 threads, 8x8 per-thread micro-tile.
// Grid: (NN/128=64, 1024/128=8)
// ---------------------------------------------------------------------------
__global__ void __launch_bounds__(256)
gemm_cheby(const float* __restrict__ A, int src, int prev, int dst, float alpha) {
    const float* X = g_X[src];
    float*       C = g_X[dst];
    const float* P = (prev >= 0) ? g_X[prev] : nullptr;

    __shared__ float As[8][128];   // A tile, transposed (k-major)
    __shared__ float Bs[8][128];   // X tile

    int tid     = threadIdx.x;
    int rowTile = blockIdx.y * 128;
    int colTile = blockIdx.x * 128;
    int ty = tid >> 4;             // 0..15 (row group)
    int tx = tid & 15;             // 0..15 (col group)

    // A tile loader: 128 rows x 8 k, one float4 per thread
    int aRow = tid >> 1;           // 0..127
    int aC4  = (tid & 1) * 4;      // 0 or 4
    // X tile loader: 8 k x 128 cols, one float4 per thread
    int bRow = tid >> 5;           // 0..7
    int bC4  = (tid & 31) * 4;     // 0..124

    const float* Ab = A + rowTile * 1024;
    const float* Xb = X + colTile;

    float acc[8][8] = {};

    for (int k0 = 0; k0 < 1024; k0 += 8) {
        float4 av = *reinterpret_cast<const float4*>(Ab + aRow * 1024 + k0 + aC4);
        As[aC4 + 0][aRow] = av.x;
        As[aC4 + 1][aRow] = av.y;
        As[aC4 + 2][aRow] = av.z;
        As[aC4 + 3][aRow] = av.w;
        float4 bv = *reinterpret_cast<const float4*>(Xb + (k0 + bRow) * NN + bC4);
        *reinterpret_cast<float4*>(&Bs[bRow][bC4]) = bv;
        __syncthreads();

        #pragma unroll
        for (int kk = 0; kk < 8; kk++) {
            float ar[8], br[8];
            #pragma unroll
            for (int i = 0; i < 8; i++) ar[i] = As[kk][ty * 8 + i];
            #pragma unroll
            for (int j = 0; j < 8; j++) br[j] = Bs[kk][tx * 8 + j];
            #pragma unroll
            for (int i = 0; i < 8; i++)
                #pragma unroll
                for (int j = 0; j < 8; j++)
                    acc[i][j] = fmaf(ar[i], br[j], acc[i][j]);
        }
        __syncthreads();
    }

    // Epilogue: C = alpha*acc - P   (float4 stores)
    #pragma unroll
    for (int i = 0; i < 8; i++) {
        int gr = rowTile + ty * 8 + i;
        float* Cp = C + gr * NN + colTile + tx * 8;
        float4 v0, v1;
        v0.x = alpha * acc[i][0]; v0.y = alpha * acc[i][1];
        v0.z = alpha * acc[i][2]; v0.w = alpha * acc[i][3];
        v1.x = alpha * acc[i][4]; v1.y = alpha * acc[i][5];
        v1.z = alpha * acc[i][6]; v1.w = alpha * acc[i][7];
        if (P) {
            const float4* Pp = reinterpret_cast<const float4*>(P + gr * NN + colTile + tx * 8);
            float4 p0 = Pp[0], p1 = Pp[1];
            v0.x -= p0.x; v0.y -= p0.y; v0.z -= p0.z; v0.w -= p0.w;
            v1.x -= p1.x; v1.y -= p1.y; v1.z -= p1.z; v1.w -= p1.w;
        }
        reinterpret_cast<float4*>(Cp)[0] = v0;
        reinterpret_cast<float4*>(Cp)[1] = v1;
    }
}

// ---------------------------------------------------------------------------
// Kernel 3: output projection + bias + layout transpose
//   out[(b, n*128+o)] = sum_m sum_f g_X[m][n][b][f] * weight[f*5+m][o] + bias[o]
// Viewed as GEMM: rows r = n*64+b (65536), cols o (128), K = 5*128, where
// Y_m = g_X[m] is exactly row-major [65536,128].
// Tile: BM=128, BN=128 (all cols), BK=8. Grid: 512 blocks.
// ---------------------------------------------------------------------------
__global__ void __launch_bounds__(256)
final_gemm(const float* __restrict__ weight, const float* __restrict__ biases,
           float* __restrict__ out) {
    __shared__ float Xs[8][128];   // Y tile, transposed (f-major)
    __shared__ float Ws[8][128];   // W tile

    int tid     = threadIdx.x;
    int rowTile = blockIdx.x * 128;
    int ty = tid >> 4;
    int tx = tid & 15;

    int lRow = tid >> 1;           // 0..127
    int lC4  = (tid & 1) * 4;      // 0 or 4
    int wRow = tid >> 5;           // 0..7
    int wC4  = (tid & 31) * 4;     // 0..124

    float acc[8][8] = {};

    #pragma unroll
    for (int m = 0; m < NUM_M; m++) {
        const float* Y = g_X[m];
        for (int f0 = 0; f0 < F_DIM; f0 += 8) {
            float4 xv = *reinterpret_cast<const float4*>(
                Y + (rowTile + lRow) * F_DIM + f0 + lC4);
            Xs[lC4 + 0][lRow] = xv.x;
            Xs[lC4 + 1][lRow] = xv.y;
            Xs[lC4 + 2][lRow] = xv.z;
            Xs[lC4 + 3][lRow] = xv.w;
            float4 wv = *reinterpret_cast<const float4*>(
                weight + ((f0 + wRow) * NUM_M + m) * OUT_DIM + wC4);
            *reinterpret_cast<float4*>(&Ws[wRow][wC4]) = wv;
            __syncthreads();

            #pragma unroll
            for (int kk = 0; kk < 8; kk++) {
                float ar[8], br[8];
                #pragma unroll
                for (int i = 0; i < 8; i++) ar[i] = Xs[kk][ty * 8 + i];
                #pragma unroll
                for (int j = 0; j < 8; j++) br[j] = Ws[kk][tx * 8 + j];
                #pragma unroll
                for (int i = 0; i < 8; i++)
                    #pragma unroll
                    for (int j = 0; j < 8; j++)
                        acc[i][j] = fmaf(ar[i], br[j], acc[i][j]);
            }
            __syncthreads();
        }
    }

    float bi[8];
    #pragma unroll
    for (int j = 0; j < 8; j++) bi[j] = biases[tx * 8 + j];

    #pragma unroll
    for (int i = 0; i < 8; i++) {
        int gr = rowTile + ty * 8 + i;
        int n = gr >> 6;           // row index r = n*64 + b
        int b = gr & 63;
        float* op = out + b * (N_NODES * OUT_DIM) + n * OUT_DIM + tx * 8;
        float4 v0, v1;
        v0.x = acc[i][0] + bi[0]; v0.y = acc[i][1] + bi[1];
        v0.z = acc[i][2] + bi[2]; v0.w = acc[i][3] + bi[3];
        v1.x = acc[i][4] + bi[4]; v1.y = acc[i][5] + bi[5];
        v1.z = acc[i][6] + bi[6]; v1.w = acc[i][7] + bi[7];
        reinterpret_cast<float4*>(op)[0] = v0;
        reinterpret_cast<float4*>(op)[1] = v1;
    }
}

// ---------------------------------------------------------------------------
// Launch: build X0, then 4 Chebyshev diffusion GEMMs, then output GEMM.
// xs order: [x0, x1_s0, x2_s0, x1_s1, x2_s1]  -> g_X slots 0..4
// ---------------------------------------------------------------------------
extern "C" void kernel_launch(void* const* d_in, const int* in_sizes, int n_in,
                              void* d_out, int out_size) {
    const float* supports = (const float*)d_in[0];  // [2, 1024, 1024]
    const float* inputs   = (const float*)d_in[1];  // [64, 65536]
    const float* state    = (const float*)d_in[2];  // [64, 65536]
    const float* weight   = (const float*)d_in[3];  // [640, 128]
    const float* biases   = (const float*)d_in[4];  // [128]
    float* out = (float*)d_out;                     // [64, 131072]

    const float* A0 = supports;
    const float* A1 = supports + N_NODES * N_NODES;

    build_x0<<<8192, 256>>>(inputs, state);

    dim3 gd(NN / 128, N_NODES / 128);  // (64, 8)
    // support 0: x1 = A0 @ x0 ; x2 = 2*A0 @ x1 - x0
    gemm_cheby<<<gd, 256>>>(A0, 0, -1, 1, 1.0f);
    gemm_cheby<<<gd, 256>>>(A0, 1,  0, 2, 2.0f);
    // support 1: x1 = A1 @ x0 ; x2 = 2*A1 @ x1 - x0
    gemm_cheby<<<gd, 256>>>(A1, 0, -1, 3, 1.0f);
    gemm_cheby<<<gd, 256>>>(A1, 3,  0, 4, 2.0f);

    final_gemm<<<512, 256>>>(weight, biases, out);
}

// round 4
// speedup vs baseline: 2.1147x; 2.1147x over previous
#include <cuda_runtime.h>
#include <cuda_bf16.h>
#include <stdint.h>

// ---------------------------------------------------------------------------
// Problem constants
// ---------------------------------------------------------------------------
#define N_NODES 1024
#define NN      8192        // BATCH(64) * F(128)
#define OUT_DIM 128
#define PLANE   (N_NODES * NN)   // 8,388,608 elements

// Global scratch (static __device__ arrays — allowed; no alloc APIs).
// Split-bf16 representation: value ~= hi + lo  (error ~2^-17 relative)
__device__ __align__(16) __nv_bfloat16 g_AsH[2][N_NODES * N_NODES]; // supports hi
__device__ __align__(16) __nv_bfloat16 g_AsL[2][N_NODES * N_NODES]; // supports lo
__device__ __align__(16) __nv_bfloat16 g_XnH[5][PLANE];  // states node-major [node][col]
__device__ __align__(16) __nv_bfloat16 g_XnL[5][PLANE];
__device__ __align__(16) __nv_bfloat16 g_XtH[3][PLANE];  // states transposed [col][node] (x0, x1s0, x1s1)
__device__ __align__(16) __nv_bfloat16 g_XtL[3][PLANE];
__device__ __align__(16) __nv_bfloat16 g_WtH[5][128 * 128]; // Wt[m][o][f]
__device__ __align__(16) __nv_bfloat16 g_WtL[5][128 * 128];

// ---------------------------------------------------------------------------
// PTX helpers (sm_80-compatible: cp.async + ldmatrix + mma.sync bf16)
// ---------------------------------------------------------------------------
__device__ __forceinline__ uint32_t smem_u32(const void* p) {
    uint32_t a;
    asm("{ .reg .u64 t; cvta.to.shared.u64 t, %1; cvt.u32.u64 %0, t; }" : "=r"(a) : "l"(p));
    return a;
}
__device__ __forceinline__ void cp16(uint32_t dst, const void* src) {
    asm volatile("cp.async.cg.shared.global [%0], [%1], 16;" :: "r"(dst), "l"(src));
}
__device__ __forceinline__ void cp_commit() {
    asm volatile("cp.async.commit_group;" ::: "memory");
}
__device__ __forceinline__ void cp_wait1() {
    asm volatile("cp.async.wait_group 1;" ::: "memory");
}
__device__ __forceinline__ void ldsm4(uint32_t& r0, uint32_t& r1, uint32_t& r2, uint32_t& r3,
                                      uint32_t addr) {
    asm volatile("ldmatrix.sync.aligned.m8n8.x4.shared.b16 {%0,%1,%2,%3}, [%4];"
                 : "=r"(r0), "=r"(r1), "=r"(r2), "=r"(r3) : "r"(addr));
}
__device__ __forceinline__ void mma16816(float* c, const uint32_t* a, const uint32_t* b) {
    asm volatile(
        "mma.sync.aligned.m16n8k16.row.col.f32.bf16.bf16.f32 "
        "{%0,%1,%2,%3}, {%4,%5,%6,%7}, {%8,%9}, {%0,%1,%2,%3};"
        : "+f"(c[0]), "+f"(c[1]), "+f"(c[2]), "+f"(c[3])
        : "r"(a[0]), "r"(a[1]), "r"(a[2]), "r"(a[3]), "r"(b[0]), "r"(b[1]));
}

__device__ __forceinline__ uint32_t packbf2(__nv_bfloat16 a, __nv_bfloat16 b) {
    __nv_bfloat162 t; t.x = a; t.y = b;
    return *reinterpret_cast<uint32_t*>(&t);
}
// split float pair -> (hi packed, lo packed)
__device__ __forceinline__ void split2(float x, float y, uint32_t& h, uint32_t& l) {
    __nv_bfloat16 hx = __float2bfloat16(x);
    __nv_bfloat16 hy = __float2bfloat16(y);
    __nv_bfloat16 lx = __float2bfloat16(x - __bfloat162float(hx));
    __nv_bfloat16 ly = __float2bfloat16(y - __bfloat162float(hy));
    h = packbf2(hx, hy);
    l = packbf2(lx, ly);
}

// ---------------------------------------------------------------------------
// SMEM layout: per stage 4 planes (Ah, Al, Bh, Bl), each [128 rows][32 k] bf16
// padded to 80 B/row (conflict-free for ldmatrix: start word 20r mod 32 distinct)
// ---------------------------------------------------------------------------
#define SM_ROW   80
#define SM_PLANE (128 * SM_ROW)     // 10240 B
#define SM_STAGE (4 * SM_PLANE)     // 40960 B
#define SM_TOTAL (3 * SM_STAGE)     // 122880 B

// copy one [128 x 32] bf16 tile into a smem plane (2x 16B per thread, 256 thr)
__device__ __forceinline__ void issue_plane(uint32_t smp, const __nv_bfloat16* src,
                                            int strideElems, int tid) {
    #pragma unroll
    for (int j = 0; j < 2; j++) {
        int id  = tid + j * 256;
        int row = id >> 2;
        int ch  = id & 3;
        cp16(smp + row * SM_ROW + ch * 16,
             (const char*)(src + (size_t)row * strideElems) + ch * 16);
    }
}

// ---------------------------------------------------------------------------
// Shared mainloop compute: one stage (BK=32), accumulate 3-term split MMAs.
// Warp layout: 8 warps = 2 (m) x 4 (n); warp tile 64 x 32.
// ---------------------------------------------------------------------------
struct WarpCoords {
    int m0, n0;
    int a_row, a_byte;   // lane-level ldmatrix addressing
    int b_row, b_byte;
};
__device__ __forceinline__ WarpCoords warp_coords(int tid) {
    WarpCoords w;
    int wid = tid >> 5, lane = tid & 31;
    int wm = wid >> 2, wn = wid & 3;
    w.m0 = wm * 64;
    w.n0 = wn * 32;
    w.a_row  = w.m0 + (lane & 7) + ((lane >> 3) & 1) * 8;
    w.a_byte = (lane >> 4) * 16;
    w.b_row  = w.n0 + ((lane >> 4) << 3) + (lane & 7);
    w.b_byte = ((lane >> 3) & 1) * 16;
    return w;
}

__device__ __forceinline__ void compute_stage(uint32_t st, const WarpCoords& w,
                                              float acc[4][4][4]) {
    #pragma unroll
    for (int ks = 0; ks < 2; ks++) {
        uint32_t ah[4][4], al[4][4], bh[4][2], bl[4][2];
        #pragma unroll
        for (int mt = 0; mt < 4; mt++) {
            uint32_t ad = st + (uint32_t)(w.a_row + mt * 16) * SM_ROW + ks * 32 + w.a_byte;
            ldsm4(ah[mt][0], ah[mt][1], ah[mt][2], ah[mt][3], ad);
            ldsm4(al[mt][0], al[mt][1], al[mt][2], al[mt][3], ad + SM_PLANE);
        }
        #pragma unroll
        for (int np = 0; np < 2; np++) {
            uint32_t bd = st + 2 * SM_PLANE +
                          (uint32_t)(w.b_row + np * 16) * SM_ROW + ks * 32 + w.b_byte;
            uint32_t t0, t1, t2, t3;
            ldsm4(t0, t1, t2, t3, bd);
            bh[2 * np][0] = t0; bh[2 * np][1] = t1;
            bh[2 * np + 1][0] = t2; bh[2 * np + 1][1] = t3;
            ldsm4(t0, t1, t2, t3, bd + SM_PLANE);
            bl[2 * np][0] = t0; bl[2 * np][1] = t1;
            bl[2 * np + 1][0] = t2; bl[2 * np + 1][1] = t3;
        }
        #pragma unroll
        for (int mt = 0; mt < 4; mt++)
            #pragma unroll
            for (int nt = 0; nt < 4; nt++) {
                mma16816(acc[mt][nt], ah[mt], bh[nt]);
                mma16816(acc[mt][nt], ah[mt], bl[nt]);
                mma16816(acc[mt][nt], al[mt], bh[nt]);
            }
    }
}

// ---------------------------------------------------------------------------
// Kernel: diffusion GEMM  D[node][col] = alpha * sum_k A[node][k]*Xt[col][k] - prev
//   A = split supports (row-major, k contiguous), B = split Xt (k contiguous).
// Grid (64 colTiles, 8 nodeTiles), 256 threads, 120 KB dyn smem.
// ---------------------------------------------------------------------------
__global__ void __launch_bounds__(256)
gemm_cheby_mma(int s, int srcT, int prevN, int dstN, int dstT, float alpha) {
    extern __shared__ __align__(128) char smem[];
    uint32_t sb = smem_u32(smem);
    int tid = threadIdx.x;
    int colTile  = blockIdx.x * 128;
    int nodeTile = blockIdx.y * 128;

    const __nv_bfloat16* Ah = g_AsH[s] + (size_t)nodeTile * N_NODES;
    const __nv_bfloat16* Al = g_AsL[s] + (size_t)nodeTile * N_NODES;
    const __nv_bfloat16* Bh = g_XtH[srcT] + (size_t)colTile * N_NODES;
    const __nv_bfloat16* Bl = g_XtL[srcT] + (size_t)colTile * N_NODES;

    const int NIT = N_NODES / 32;   // 32

    // prologue: stages 0,1
    #pragma unroll
    for (int p = 0; p < 2; p++) {
        uint32_t st = sb + p * SM_STAGE;
        int k0 = p * 32;
        issue_plane(st,                Ah + k0, N_NODES, tid);
        issue_plane(st + SM_PLANE,     Al + k0, N_NODES, tid);
        issue_plane(st + 2 * SM_PLANE, Bh + k0, N_NODES, tid);
        issue_plane(st + 3 * SM_PLANE, Bl + k0, N_NODES, tid);
        cp_commit();
    }

    WarpCoords w = warp_coords(tid);
    float acc[4][4][4] = {};

    for (int it = 0; it < NIT; it++) {
        cp_wait1();
        __syncthreads();
        if (it + 2 < NIT) {
            uint32_t st = sb + ((it + 2) % 3) * SM_STAGE;
            int k0 = (it + 2) * 32;
            issue_plane(st,                Ah + k0, N_NODES, tid);
            issue_plane(st + SM_PLANE,     Al + k0, N_NODES, tid);
            issue_plane(st + 2 * SM_PLANE, Bh + k0, N_NODES, tid);
            issue_plane(st + 3 * SM_PLANE, Bl + k0, N_NODES, tid);
        }
        cp_commit();
        compute_stage(sb + (it % 3) * SM_STAGE, w, acc);
    }

    // Epilogue: v = alpha*acc - (prevH+prevL); write split node-major (+transposed).
    int lane = tid & 31;
    int l4 = lane >> 2, lp = lane & 3;
    #pragma unroll
    for (int mt = 0; mt < 4; mt++) {
        #pragma unroll
        for (int nt = 0; nt < 4; nt++) {
            int col = colTile + w.n0 + nt * 8 + lp * 2;
            #pragma unroll
            for (int h = 0; h < 2; h++) {
                int node = nodeTile + w.m0 + mt * 16 + l4 + h * 8;
                float vx = alpha * acc[mt][nt][h * 2 + 0];
                float vy = alpha * acc[mt][nt][h * 2 + 1];
                size_t off = (size_t)node * NN + col;
                if (prevN >= 0) {
                    __nv_bfloat162 ph = *reinterpret_cast<const __nv_bfloat162*>(&g_XnH[prevN][off]);
                    __nv_bfloat162 pl = *reinterpret_cast<const __nv_bfloat162*>(&g_XnL[prevN][off]);
                    vx -= __bfloat162float(ph.x) + __bfloat162float(pl.x);
                    vy -= __bfloat162float(ph.y) + __bfloat162float(pl.y);
                }
                uint32_t hp, lpk;
                split2(vx, vy, hp, lpk);
                *reinterpret_cast<uint32_t*>(&g_XnH[dstN][off]) = hp;
                *reinterpret_cast<uint32_t*>(&g_XnL[dstN][off]) = lpk;
                if (dstT >= 0) {
                    __nv_bfloat162 H = *reinterpret_cast<__nv_bfloat162*>(&hp);
                    __nv_bfloat162 L = *reinterpret_cast<__nv_bfloat162*>(&lpk);
                    g_XtH[dstT][(size_t)col * N_NODES + node]       = H.x;
                    g_XtH[dstT][(size_t)(col + 1) * N_NODES + node] = H.y;
                    g_XtL[dstT][(size_t)col * N_NODES + node]       = L.x;
                    g_XtL[dstT][(size_t)(col + 1) * N_NODES + node] = L.y;
                }
            }
        }
    }
}

// ---------------------------------------------------------------------------
// Kernel: final projection  out[r][o] = sum_m sum_f Xn[m][r][f]*Wt[m][o][f] + bias
//   r = node*64 + b (Xn node-major is exactly [65536][128] row-major).
// Grid 512 rTiles, 256 threads.
// ---------------------------------------------------------------------------
__global__ void __launch_bounds__(256)
final_gemm_mma(const float* __restrict__ biases, float* __restrict__ out) {
    extern __shared__ __align__(128) char smem[];
    uint32_t sb = smem_u32(smem);
    int tid = threadIdx.x;
    int rTile = blockIdx.x * 128;

    const int NIT = 20;   // 5 planes x 4 k-chunks of 32

    #pragma unroll
    for (int p = 0; p < 2; p++) {
        uint32_t st = sb + p * SM_STAGE;
        int m = p >> 2, f0 = (p & 3) * 32;
        issue_plane(st,                g_XnH[m] + (size_t)rTile * 128 + f0, 128, tid);
        issue_plane(st + SM_PLANE,     g_XnL[m] + (size_t)rTile * 128 + f0, 128, tid);
        issue_plane(st + 2 * SM_PLANE, g_WtH[m] + f0, 128, tid);
        issue_plane(st + 3 * SM_PLANE, g_WtL[m] + f0, 128, tid);
        cp_commit();
    }

    WarpCoords w = warp_coords(tid);
    float acc[4][4][4] = {};

    for (int it = 0; it < NIT; it++) {
        cp_wait1();
        __syncthreads();
        if (it + 2 < NIT) {
            int nx = it + 2;
            uint32_t st = sb + (nx % 3) * SM_STAGE;
            int m = nx >> 2, f0 = (nx & 3) * 32;
            issue_plane(st,                g_XnH[m] + (size_t)rTile * 128 + f0, 128, tid);
            issue_plane(st + SM_PLANE,     g_XnL[m] + (size_t)rTile * 128 + f0, 128, tid);
            issue_plane(st + 2 * SM_PLANE, g_WtH[m] + f0, 128, tid);
            issue_plane(st + 3 * SM_PLANE, g_WtL[m] + f0, 128, tid);
        }
        cp_commit();
        compute_stage(sb + (it % 3) * SM_STAGE, w, acc);
    }

    int lane = tid & 31;
    int l4 = lane >> 2, lp = lane & 3;
    #pragma unroll
    for (int mt = 0; mt < 4; mt++) {
        #pragma unroll
        for (int nt = 0; nt < 4; nt++) {
            int o = w.n0 + nt * 8 + lp * 2;
            float b0 = biases[o], b1 = biases[o + 1];
            #pragma unroll
            for (int h = 0; h < 2; h++) {
                int r = rTile + w.m0 + mt * 16 + l4 + h * 8;
                int b = r & 63, n = r >> 6;
                float2 v;
                v.x = acc[mt][nt][h * 2 + 0] + b0;
                v.y = acc[mt][nt][h * 2 + 1] + b1;
                *reinterpret_cast<float2*>(&out[(size_t)b * (N_NODES * OUT_DIM) + n * OUT_DIM + o]) = v;
            }
        }
    }
}

// ---------------------------------------------------------------------------
// Prep kernels
// ---------------------------------------------------------------------------
// supports fp32 [2*1024*1024] -> split bf16 planes (flat)
__global__ void split_supports(const float* __restrict__ sup) {
    int idx = blockIdx.x * blockDim.x + threadIdx.x;   // float4 index, 524288 total
    float4 v = reinterpret_cast<const float4*>(sup)[idx];
    uint32_t h0, l0, h1, l1;
    split2(v.x, v.y, h0, l0);
    split2(v.z, v.w, h1, l1);
    uint2 H = make_uint2(h0, h1), L = make_uint2(l0, l1);
    reinterpret_cast<uint2*>(&g_AsH[0][0])[idx] = H;
    reinterpret_cast<uint2*>(&g_AsL[0][0])[idx] = L;
}

// x0 node-major split: g_Xn[0][n][b*128+f] = concat(inputs[b][n][:], state[b][n][:])
__global__ void build_x0_split(const float* __restrict__ inputs,
                               const float* __restrict__ state) {
    int idx = blockIdx.x * blockDim.x + threadIdx.x;   // float4 index, 2097152 total
    int f4 = idx & 31;
    int b  = (idx >> 5) & 63;
    int n  = idx >> 11;
    float4 v;
    if (f4 < 16)
        v = reinterpret_cast<const float4*>(inputs)[b * 16384 + n * 16 + f4];
    else
        v = reinterpret_cast<const float4*>(state )[b * 16384 + n * 16 + (f4 - 16)];
    uint32_t h0, l0, h1, l1;
    split2(v.x, v.y, h0, l0);
    split2(v.z, v.w, h1, l1);
    reinterpret_cast<uint2*>(&g_XnH[0][0])[idx] = make_uint2(h0, h1);
    reinterpret_cast<uint2*>(&g_XnL[0][0])[idx] = make_uint2(l0, l1);
}

// transpose x0 planes: [node][col] -> [col][node]  (z = 0:hi, 1:lo)
__global__ void transpose_x0() {
    __shared__ __nv_bfloat16 t[32][33];
    const __nv_bfloat16* S = blockIdx.z ? g_XnL[0] : g_XnH[0];
    __nv_bfloat16*       D = blockIdx.z ? g_XtL[0] : g_XtH[0];
    int bx = blockIdx.x, by = blockIdx.y;   // bx: 256 col tiles, by: 32 node tiles
    int x = threadIdx.x, y = threadIdx.y;
    #pragma unroll
    for (int i = 0; i < 32; i += 8)
        t[y + i][x] = S[(size_t)(by * 32 + y + i) * NN + bx * 32 + x];
    __syncthreads();
    #pragma unroll
    for (int i = 0; i < 32; i += 8)
        D[(size_t)(bx * 32 + y + i) * N_NODES + by * 32 + x] = t[x][y + i];
}

// Wt[m][o][f] = weight[(f*5+m)][o], split
__global__ void prep_w_split(const float* __restrict__ wsrc) {
    int idx = blockIdx.x * blockDim.x + threadIdx.x;   // 81920 total
    int m = idx / 16384;
    int rem = idx % 16384;
    int o = rem / 128;
    int f = rem % 128;
    float v = wsrc[(f * 5 + m) * 128 + o];
    __nv_bfloat16 h = __float2bfloat16(v);
    __nv_bfloat16 l = __float2bfloat16(v - __bfloat162float(h));
    g_WtH[0][idx] = h;   // [m][o*128+f] flattened == idx layout
    g_WtL[0][idx] = l;
}

// ---------------------------------------------------------------------------
// Launch
// ---------------------------------------------------------------------------
extern "C" void kernel_launch(void* const* d_in, const int* in_sizes, int n_in,
                              void* d_out, int out_size) {
    const float* supports = (const float*)d_in[0];  // [2,1024,1024]
    const float* inputs   = (const float*)d_in[1];  // [64, 65536]
    const float* state    = (const float*)d_in[2];  // [64, 65536]
    const float* weight   = (const float*)d_in[3];  // [640, 128]
    const float* biases   = (const float*)d_in[4];  // [128]
    float* out = (float*)d_out;                     // [64, 131072]

    cudaFuncSetAttribute(gemm_cheby_mma, cudaFuncAttributeMaxDynamicSharedMemorySize, SM_TOTAL);
    cudaFuncSetAttribute(final_gemm_mma, cudaFuncAttributeMaxDynamicSharedMemorySize, SM_TOTAL);

    split_supports<<<2048, 256>>>(supports);
    build_x0_split<<<8192, 256>>>(inputs, state);
    transpose_x0<<<dim3(256, 32, 2), dim3(32, 8)>>>();
    prep_w_split<<<320, 256>>>(weight);

    dim3 gd(NN / 128, N_NODES / 128);   // (64, 8)
    // support 0: x1 = A0@x0 ; x2 = 2*A0@x1 - x0
    gemm_cheby_mma<<<gd, 256, SM_TOTAL>>>(0, 0, -1, 1, 1, 1.0f);
    gemm_cheby_mma<<<gd, 256, SM_TOTAL>>>(0, 1,  0, 2, -1, 2.0f);
    // support 1: x1 = A1@x0 ; x2 = 2*A1@x1 - x0
    gemm_cheby_mma<<<gd, 256, SM_TOTAL>>>(1, 0, -1, 3, 2, 1.0f);
    gemm_cheby_mma<<<gd, 256, SM_TOTAL>>>(1, 2,  0, 4, -1, 2.0f);

    final_gemm_mma<<<512, 256, SM_TOTAL>>>(biases, out);
}

// round 6
// speedup vs baseline: 3.0359x; 1.4356x over previous
#include <cuda_runtime.h>
#include <cuda_bf16.h>
#include <stdint.h>

// ---------------------------------------------------------------------------
// Problem constants
// ---------------------------------------------------------------------------
#define N_NODES 1024
#define NN      8192        // BATCH(64) * F(128)
#define OUT_DIM 128
#define PLANE   (N_NODES * NN)   // 8,388,608 elements

// Global scratch (static __device__ arrays — allowed; no alloc APIs).
// Split-bf16 representation: value ~= hi + lo  (error ~2^-17 relative)
__device__ __align__(16) __nv_bfloat16 g_AsH[2][N_NODES * N_NODES]; // supports hi
__device__ __align__(16) __nv_bfloat16 g_AsL[2][N_NODES * N_NODES]; // supports lo
__device__ __align__(16) __nv_bfloat16 g_XnH[5][PLANE];  // states node-major [node][col]
__device__ __align__(16) __nv_bfloat16 g_XnL[5][PLANE];
__device__ __align__(16) __nv_bfloat16 g_WtH[5][128 * 128]; // Wt[m][o][f]
__device__ __align__(16) __nv_bfloat16 g_WtL[5][128 * 128];

// ---------------------------------------------------------------------------
// PTX helpers (sm_80-compatible: cp.async + ldmatrix + mma.sync bf16)
// ---------------------------------------------------------------------------
__device__ __forceinline__ uint32_t smem_u32(const void* p) {
    uint32_t a;
    asm("{ .reg .u64 t; cvta.to.shared.u64 t, %1; cvt.u32.u64 %0, t; }" : "=r"(a) : "l"(p));
    return a;
}
__device__ __forceinline__ void cp16(uint32_t dst, const void* src) {
    asm volatile("cp.async.cg.shared.global [%0], [%1], 16;" :: "r"(dst), "l"(src));
}
__device__ __forceinline__ void cp_commit() {
    asm volatile("cp.async.commit_group;" ::: "memory");
}
__device__ __forceinline__ void cp_wait1() {
    asm volatile("cp.async.wait_group 1;" ::: "memory");
}
__device__ __forceinline__ void ldsm4(uint32_t& r0, uint32_t& r1, uint32_t& r2, uint32_t& r3,
                                      uint32_t addr) {
    asm volatile("ldmatrix.sync.aligned.m8n8.x4.shared.b16 {%0,%1,%2,%3}, [%4];"
                 : "=r"(r0), "=r"(r1), "=r"(r2), "=r"(r3) : "r"(addr));
}
__device__ __forceinline__ void ldsm4t(uint32_t& r0, uint32_t& r1, uint32_t& r2, uint32_t& r3,
                                       uint32_t addr) {
    asm volatile("ldmatrix.sync.aligned.m8n8.x4.trans.shared.b16 {%0,%1,%2,%3}, [%4];"
                 : "=r"(r0), "=r"(r1), "=r"(r2), "=r"(r3) : "r"(addr));
}
__device__ __forceinline__ void mma16816(float* c, const uint32_t* a, const uint32_t* b) {
    asm volatile(
        "mma.sync.aligned.m16n8k16.row.col.f32.bf16.bf16.f32 "
        "{%0,%1,%2,%3}, {%4,%5,%6,%7}, {%8,%9}, {%0,%1,%2,%3};"
        : "+f"(c[0]), "+f"(c[1]), "+f"(c[2]), "+f"(c[3])
        : "r"(a[0]), "r"(a[1]), "r"(a[2]), "r"(a[3]), "r"(b[0]), "r"(b[1]));
}

__device__ __forceinline__ uint32_t packbf2(__nv_bfloat16 a, __nv_bfloat16 b) {
    __nv_bfloat162 t; t.x = a; t.y = b;
    return *reinterpret_cast<uint32_t*>(&t);
}
// split float pair -> (hi packed, lo packed)
__device__ __forceinline__ void split2(float x, float y, uint32_t& h, uint32_t& l) {
    __nv_bfloat16 hx = __float2bfloat16(x);
    __nv_bfloat16 hy = __float2bfloat16(y);
    __nv_bfloat16 lx = __float2bfloat16(x - __bfloat162float(hx));
    __nv_bfloat16 ly = __float2bfloat16(y - __bfloat162float(hy));
    h = packbf2(hx, hy);
    l = packbf2(lx, ly);
}

// ---------------------------------------------------------------------------
// SMEM layouts
// Diffusion stage: Ah/Al planes [128 m][32 k] pitch 80 B (conflict-free non-trans
// ldmatrix), Bh/Bl planes [32 k][128 n] pitch 272 B (conflict-free trans ldmatrix:
// row step 68 words ≡ 4 mod 32 → 8 rows/phase hit all 32 banks once).
// ---------------------------------------------------------------------------
#define A_PITCH 80
#define A_PLANE (128 * A_PITCH)          // 10240 B
#define B_PITCH 272
#define B_PLANE (32 * B_PITCH)           // 8704 B
#define D_OFF_AH 0
#define D_OFF_AL A_PLANE
#define D_OFF_BH (2 * A_PLANE)
#define D_OFF_BL (2 * A_PLANE + B_PLANE)
#define D_STAGE  (2 * A_PLANE + 2 * B_PLANE)   // 37888 B
#define D_TOTAL  (3 * D_STAGE)                 // 113664 B

// Final-gemm stage (unchanged from round 4): 4 planes [128 rows][32 k] pitch 80
#define F_PLANE A_PLANE
#define F_STAGE (4 * F_PLANE)            // 40960 B
#define F_TOTAL (3 * F_STAGE)            // 122880 B

// copy one [128 x 32] bf16 tile into a pitch-80 smem plane (2x 16B per thread)
__device__ __forceinline__ void issue_plane_a(uint32_t smp, const __nv_bfloat16* src,
                                              int strideElems, int tid) {
    #pragma unroll
    for (int j = 0; j < 2; j++) {
        int id  = tid + j * 256;
        int row = id >> 2;
        int ch  = id & 3;
        cp16(smp + row * A_PITCH + ch * 16,
             (const char*)(src + (size_t)row * strideElems) + ch * 16);
    }
}
// copy one [32 k x 128 n] bf16 tile into a pitch-272 smem plane
__device__ __forceinline__ void issue_plane_b(uint32_t smp, const __nv_bfloat16* src,
                                              int strideElems, int tid) {
    #pragma unroll
    for (int j = 0; j < 2; j++) {
        int id  = tid + j * 256;
        int row = id >> 4;          // 0..31 (k)
        int ch  = id & 15;          // 0..15 (16B chunks across 128 n)
        cp16(smp + row * B_PITCH + ch * 16,
             (const char*)(src + (size_t)row * strideElems) + ch * 16);
    }
}

// ---------------------------------------------------------------------------
// Warp layout: 8 warps = 2 (m) x 4 (n); warp tile 64 x 32.
// ---------------------------------------------------------------------------
struct WarpCoords {
    int m0, n0;
    int a_row, a_byte;   // non-trans ldmatrix lane addressing (A, pitch 80)
    int b_krow, b_nbyte; // trans ldmatrix lane addressing (B, pitch 272)
};
__device__ __forceinline__ WarpCoords warp_coords(int tid) {
    WarpCoords w;
    int wid = tid >> 5, lane = tid & 31;
    int wm = wid >> 2, wn = wid & 3;
    w.m0 = wm * 64;
    w.n0 = wn * 32;
    w.a_row  = w.m0 + (lane & 7) + ((lane >> 3) & 1) * 8;
    w.a_byte = (lane >> 4) * 16;
    w.b_krow = lane & 15;
    w.b_nbyte = (lane >> 4) * 16;
    return w;
}

// A fragments (non-trans) from pitch-80 [m][k] planes; B fragments (trans)
// from pitch-272 [k][n] planes. 3-term split accumulate.
__device__ __forceinline__ void compute_stage_diff(uint32_t st, const WarpCoords& w,
                                                   float acc[4][4][4]) {
    #pragma unroll
    for (int ks = 0; ks < 2; ks++) {
        uint32_t ah[4][4], al[4][4], bh[4][2], bl[4][2];
        #pragma unroll
        for (int mt = 0; mt < 4; mt++) {
            uint32_t ad = st + D_OFF_AH + (uint32_t)(w.a_row + mt * 16) * A_PITCH
                          + ks * 32 + w.a_byte;
            ldsm4(ah[mt][0], ah[mt][1], ah[mt][2], ah[mt][3], ad);
            ldsm4(al[mt][0], al[mt][1], al[mt][2], al[mt][3], ad + A_PLANE);
        }
        #pragma unroll
        for (int np = 0; np < 2; np++) {
            uint32_t bd = st + D_OFF_BH + (uint32_t)(ks * 16 + w.b_krow) * B_PITCH
                          + (uint32_t)(w.n0 + np * 16) * 2 + w.b_nbyte;
            uint32_t t0, t1, t2, t3;
            ldsm4t(t0, t1, t2, t3, bd);
            bh[2 * np][0] = t0; bh[2 * np][1] = t1;
            bh[2 * np + 1][0] = t2; bh[2 * np + 1][1] = t3;
            ldsm4t(t0, t1, t2, t3, bd + B_PLANE);
            bl[2 * np][0] = t0; bl[2 * np][1] = t1;
            bl[2 * np + 1][0] = t2; bl[2 * np + 1][1] = t3;
        }
        #pragma unroll
        for (int mt = 0; mt < 4; mt++)
            #pragma unroll
            for (int nt = 0; nt < 4; nt++) {
                mma16816(acc[mt][nt], ah[mt], bh[nt]);
                mma16816(acc[mt][nt], ah[mt], bl[nt]);
                mma16816(acc[mt][nt], al[mt], bh[nt]);
            }
    }
}

// Final-gemm variant: both operands non-trans from pitch-80 planes (round-4 code).
__device__ __forceinline__ void compute_stage_f(uint32_t st, const WarpCoords& w,
                                                int lane, float acc[4][4][4]) {
    int b_row  = w.n0 + ((lane >> 4) << 3) + (lane & 7);
    int b_byte = ((lane >> 3) & 1) * 16;
    #pragma unroll
    for (int ks = 0; ks < 2; ks++) {
        uint32_t ah[4][4], al[4][4], bh[4][2], bl[4][2];
        #pragma unroll
        for (int mt = 0; mt < 4; mt++) {
            uint32_t ad = st + (uint32_t)(w.a_row + mt * 16) * A_PITCH + ks * 32 + w.a_byte;
            ldsm4(ah[mt][0], ah[mt][1], ah[mt][2], ah[mt][3], ad);
            ldsm4(al[mt][0], al[mt][1], al[mt][2], al[mt][3], ad + F_PLANE);
        }
        #pragma unroll
        for (int np = 0; np < 2; np++) {
            uint32_t bd = st + 2 * F_PLANE +
                          (uint32_t)(b_row + np * 16) * A_PITCH + ks * 32 + b_byte;
            uint32_t t0, t1, t2, t3;
            ldsm4(t0, t1, t2, t3, bd);
            bh[2 * np][0] = t0; bh[2 * np][1] = t1;
            bh[2 * np + 1][0] = t2; bh[2 * np + 1][1] = t3;
            ldsm4(t0, t1, t2, t3, bd + F_PLANE);
            bl[2 * np][0] = t0; bl[2 * np][1] = t1;
            bl[2 * np + 1][0] = t2; bl[2 * np + 1][1] = t3;
        }
        #pragma unroll
        for (int mt = 0; mt < 4; mt++)
            #pragma unroll
            for (int nt = 0; nt < 4; nt++) {
                mma16816(acc[mt][nt], ah[mt], bh[nt]);
                mma16816(acc[mt][nt], ah[mt], bl[nt]);
                mma16816(acc[mt][nt], al[mt], bh[nt]);
            }
    }
}

// ---------------------------------------------------------------------------
// Diffusion GEMM: D[node][col] = alpha * sum_k A[node][k] * X[k(node-major row)][col] - prev
// B operand read directly from node-major Xn via trans-ldmatrix (no Xt copies).
// Grid (64 colTiles, 8 nodeTiles, 2 supports). step: 0 -> x1 = A@x0;
// 1 -> x2 = 2*A@x1 - x0.
// ---------------------------------------------------------------------------
__global__ void __launch_bounds__(256)
gemm_cheby_mma(int step) {
    extern __shared__ __align__(128) char smem[];
    uint32_t sb = smem_u32(smem);
    int tid = threadIdx.x;
    int colTile  = blockIdx.x * 128;
    int nodeTile = blockIdx.y * 128;
    int s = blockIdx.z;

    int srcN  = (step == 0) ? 0 : (1 + 2 * s);
    int prevN = (step == 0) ? -1 : 0;
    int dstN  = (step == 0) ? (1 + 2 * s) : (2 + 2 * s);
    float alpha = (step == 0) ? 1.0f : 2.0f;

    const __nv_bfloat16* Ah = g_AsH[s] + (size_t)nodeTile * N_NODES;
    const __nv_bfloat16* Al = g_AsL[s] + (size_t)nodeTile * N_NODES;
    const __nv_bfloat16* Bh = g_XnH[srcN] + colTile;   // row index = k (node)
    const __nv_bfloat16* Bl = g_XnL[srcN] + colTile;

    const int NIT = N_NODES / 32;   // 32

    #pragma unroll
    for (int p = 0; p < 2; p++) {
        uint32_t st = sb + p * D_STAGE;
        int k0 = p * 32;
        issue_plane_a(st + D_OFF_AH, Ah + k0, N_NODES, tid);
        issue_plane_a(st + D_OFF_AL, Al + k0, N_NODES, tid);
        issue_plane_b(st + D_OFF_BH, Bh + (size_t)k0 * NN, NN, tid);
        issue_plane_b(st + D_OFF_BL, Bl + (size_t)k0 * NN, NN, tid);
        cp_commit();
    }

    WarpCoords w = warp_coords(tid);
    float acc[4][4][4] = {};

    for (int it = 0; it < NIT; it++) {
        cp_wait1();
        __syncthreads();
        if (it + 2 < NIT) {
            uint32_t st = sb + ((it + 2) % 3) * D_STAGE;
            int k0 = (it + 2) * 32;
            issue_plane_a(st + D_OFF_AH, Ah + k0, N_NODES, tid);
            issue_plane_a(st + D_OFF_AL, Al + k0, N_NODES, tid);
            issue_plane_b(st + D_OFF_BH, Bh + (size_t)k0 * NN, NN, tid);
            issue_plane_b(st + D_OFF_BL, Bl + (size_t)k0 * NN, NN, tid);
        }
        cp_commit();
        compute_stage_diff(sb + (it % 3) * D_STAGE, w, acc);
    }

    // Epilogue: v = alpha*acc - (prevH+prevL); write split node-major only.
    int lane = tid & 31;
    int l4 = lane >> 2, lp = lane & 3;
    #pragma unroll
    for (int mt = 0; mt < 4; mt++) {
        #pragma unroll
        for (int nt = 0; nt < 4; nt++) {
            int col = colTile + w.n0 + nt * 8 + lp * 2;
            #pragma unroll
            for (int h = 0; h < 2; h++) {
                int node = nodeTile + w.m0 + mt * 16 + l4 + h * 8;
                float vx = alpha * acc[mt][nt][h * 2 + 0];
                float vy = alpha * acc[mt][nt][h * 2 + 1];
                size_t off = (size_t)node * NN + col;
                if (prevN >= 0) {
                    __nv_bfloat162 ph = *reinterpret_cast<const __nv_bfloat162*>(&g_XnH[prevN][off]);
                    __nv_bfloat162 pl = *reinterpret_cast<const __nv_bfloat162*>(&g_XnL[prevN][off]);
                    vx -= __bfloat162float(ph.x) + __bfloat162float(pl.x);
                    vy -= __bfloat162float(ph.y) + __bfloat162float(pl.y);
                }
                uint32_t hp, lpk;
                split2(vx, vy, hp, lpk);
                *reinterpret_cast<uint32_t*>(&g_XnH[dstN][off]) = hp;
                *reinterpret_cast<uint32_t*>(&g_XnL[dstN][off]) = lpk;
            }
        }
    }
}

// ---------------------------------------------------------------------------
// Final projection: out[r][o] = sum_m sum_f Xn[m][r][f]*Wt[m][o][f] + bias
//   r = node*64 + b (Xn node-major is exactly [65536][128] row-major).
// ---------------------------------------------------------------------------
__global__ void __launch_bounds__(256)
final_gemm_mma(const float* __restrict__ biases, float* __restrict__ out) {
    extern __shared__ __align__(128) char smem[];
    uint32_t sb = smem_u32(smem);
    int tid = threadIdx.x;
    int rTile = blockIdx.x * 128;

    const int NIT = 20;   // 5 planes x 4 k-chunks of 32

    #pragma unroll
    for (int p = 0; p < 2; p++) {
        uint32_t st = sb + p * F_STAGE;
        int m = p >> 2, f0 = (p & 3) * 32;
        issue_plane_a(st,               g_XnH[m] + (size_t)rTile * 128 + f0, 128, tid);
        issue_plane_a(st + F_PLANE,     g_XnL[m] + (size_t)rTile * 128 + f0, 128, tid);
        issue_plane_a(st + 2 * F_PLANE, g_WtH[m] + f0, 128, tid);
        issue_plane_a(st + 3 * F_PLANE, g_WtL[m] + f0, 128, tid);
        cp_commit();
    }

    WarpCoords w = warp_coords(tid);
    int lane = tid & 31;
    float acc[4][4][4] = {};

    for (int it = 0; it < NIT; it++) {
        cp_wait1();
        __syncthreads();
        if (it + 2 < NIT) {
            int nx = it + 2;
            uint32_t st = sb + (nx % 3) * F_STAGE;
            int m = nx >> 2, f0 = (nx & 3) * 32;
            issue_plane_a(st,               g_XnH[m] + (size_t)rTile * 128 + f0, 128, tid);
            issue_plane_a(st + F_PLANE,     g_XnL[m] + (size_t)rTile * 128 + f0, 128, tid);
            issue_plane_a(st + 2 * F_PLANE, g_WtH[m] + f0, 128, tid);
            issue_plane_a(st + 3 * F_PLANE, g_WtL[m] + f0, 128, tid);
        }
        cp_commit();
        compute_stage_f(sb + (it % 3) * F_STAGE, w, lane, acc);
    }

    int l4 = lane >> 2, lp = lane & 3;
    #pragma unroll
    for (int mt = 0; mt < 4; mt++) {
        #pragma unroll
        for (int nt = 0; nt < 4; nt++) {
            int o = w.n0 + nt * 8 + lp * 2;
            float b0 = biases[o], b1 = biases[o + 1];
            #pragma unroll
            for (int h = 0; h < 2; h++) {
                int r = rTile + w.m0 + mt * 16 + l4 + h * 8;
                int b = r & 63, n = r >> 6;
                float2 v;
                v.x = acc[mt][nt][h * 2 + 0] + b0;
                v.y = acc[mt][nt][h * 2 + 1] + b1;
                *reinterpret_cast<float2*>(&out[(size_t)b * (N_NODES * OUT_DIM) + n * OUT_DIM + o]) = v;
            }
        }
    }
}

// ---------------------------------------------------------------------------
// Prep kernels
// ---------------------------------------------------------------------------
__global__ void split_supports(const float* __restrict__ sup) {
    int idx = blockIdx.x * blockDim.x + threadIdx.x;   // float4 index, 524288 total
    float4 v = reinterpret_cast<const float4*>(sup)[idx];
    uint32_t h0, l0, h1, l1;
    split2(v.x, v.y, h0, l0);
    split2(v.z, v.w, h1, l1);
    reinterpret_cast<uint2*>(&g_AsH[0][0])[idx] = make_uint2(h0, h1);
    reinterpret_cast<uint2*>(&g_AsL[0][0])[idx] = make_uint2(l0, l1);
}

__global__ void build_x0_split(const float* __restrict__ inputs,
                               const float* __restrict__ state) {
    int idx = blockIdx.x * blockDim.x + threadIdx.x;   // float4 index, 2097152 total
    int f4 = idx & 31;
    int b  = (idx >> 5) & 63;
    int n  = idx >> 11;
    float4 v;
    if (f4 < 16)
        v = reinterpret_cast<const float4*>(inputs)[b * 16384 + n * 16 + f4];
    else
        v = reinterpret_cast<const float4*>(state )[b * 16384 + n * 16 + (f4 - 16)];
    uint32_t h0, l0, h1, l1;
    split2(v.x, v.y, h0, l0);
    split2(v.z, v.w, h1, l1);
    reinterpret_cast<uint2*>(&g_XnH[0][0])[idx] = make_uint2(h0, h1);
    reinterpret_cast<uint2*>(&g_XnL[0][0])[idx] = make_uint2(l0, l1);
}

// Wt[m][o][f] = weight[(f*5+m)][o], split
__global__ void prep_w_split(const float* __restrict__ wsrc) {
    int idx = blockIdx.x * blockDim.x + threadIdx.x;   // 81920 total
    int m = idx / 16384;
    int rem = idx % 16384;
    int o = rem / 128;
    int f = rem % 128;
    float v = wsrc[(f * 5 + m) * 128 + o];
    __nv_bfloat16 h = __float2bfloat16(v);
    __nv_bfloat16 l = __float2bfloat16(v - __bfloat162float(h));
    g_WtH[0][idx] = h;
    g_WtL[0][idx] = l;
}

// ---------------------------------------------------------------------------
// Launch
// ---------------------------------------------------------------------------
extern "C" void kernel_launch(void* const* d_in, const int* in_sizes, int n_in,
                              void* d_out, int out_size) {
    const float* supports = (const float*)d_in[0];  // [2,1024,1024]
    const float* inputs   = (const float*)d_in[1];  // [64, 65536]
    const float* state    = (const float*)d_in[2];  // [64, 65536]
    const float* weight   = (const float*)d_in[3];  // [640, 128]
    const float* biases   = (const float*)d_in[4];  // [128]
    float* out = (float*)d_out;                     // [64, 131072]

    cudaFuncSetAttribute(gemm_cheby_mma, cudaFuncAttributeMaxDynamicSharedMemorySize, D_TOTAL);
    cudaFuncSetAttribute(final_gemm_mma, cudaFuncAttributeMaxDynamicSharedMemorySize, F_TOTAL);

    split_supports<<<2048, 256>>>(supports);
    build_x0_split<<<8192, 256>>>(inputs, state);
    prep_w_split<<<320, 256>>>(weight);

    dim3 gd(NN / 128, N_NODES / 128, 2);   // (64, 8, 2) — both supports per step
    gemm_cheby_mma<<<gd, 256, D_TOTAL>>>(0);   // x1_s = A_s @ x0
    gemm_cheby_mma<<<gd, 256, D_TOTAL>>>(1);   // x2_s = 2*A_s @ x1_s - x0

    final_gemm_mma<<<512, 256, F_TOTAL>>>(biases, out);
}